// round 15
// baseline (speedup 1.0000x reference)
#include <cuda_runtime.h>
#include <cuda_bf16.h>

// IrradiationSingleTimestep — round 15: barrier-free warp-strip rolling stencil
// with Blackwell packed f32x2 math (FFMA2/FADD2/FMUL2 via PTX *.f32x2).
// Structure identical to round 12 (RPB=16, unroll 2, deep prefetch); the
// per-point arithmetic is reworked to packed pairs, __log2f with ln2 folded
// into kBT, and __saturatef clamps.

#define W     1024
#define BAT   8
#define RPB   16
#define EPSV  1e-6f
#define DTV   1e-2f
#define LN2F  0.6931471805599453f

typedef unsigned long long u64;

__device__ __forceinline__ u64 pk(float a, float b) {
    u64 r; asm("mov.b64 %0,{%1,%2};" : "=l"(r) : "f"(a), "f"(b)); return r;
}
__device__ __forceinline__ void upk(u64 v, float& a, float& b) {
    asm("mov.b64 {%0,%1},%2;" : "=f"(a), "=f"(b) : "l"(v));
}
__device__ __forceinline__ u64 add2(u64 a, u64 b) {
    u64 r; asm("add.rn.f32x2 %0,%1,%2;" : "=l"(r) : "l"(a), "l"(b)); return r;
}
__device__ __forceinline__ u64 mul2(u64 a, u64 b) {
    u64 r; asm("mul.rn.f32x2 %0,%1,%2;" : "=l"(r) : "l"(a), "l"(b)); return r;
}
__device__ __forceinline__ u64 fma2(u64 a, u64 b, u64 c) {
    u64 r; asm("fma.rn.f32x2 %0,%1,%2,%3;" : "=l"(r) : "l"(a), "l"(b), "l"(c)); return r;
}

struct Row { u64 p0, p1; };   // (x,y),(z,w)

__global__ __launch_bounds__(128, 4)
void irr_warp_kernel(const float* __restrict__ cv_g,
                     const float* __restrict__ ci_g,
                     const float* __restrict__ eta_g,
                     const float* __restrict__ p_ev,
                     const float* __restrict__ p_ei,
                     const float* __restrict__ p_kbt,
                     const float* __restrict__ p_kv,
                     const float* __restrict__ p_ki,
                     const float* __restrict__ p_ke,
                     const float* __restrict__ p_dv,
                     const float* __restrict__ p_di,
                     const float* __restrict__ p_L,
                     float* __restrict__ out)
{
    const int lane  = threadIdx.x & 31;
    const int wl    = threadIdx.x >> 5;
    const int strip = blockIdx.x * 4 + wl;
    const int x     = (strip << 7) + (lane << 2);
    const int y0    = blockIdx.y * RPB;
    const int b     = blockIdx.z;

    const size_t plane = (size_t)W * W;
    const size_t fld   = (size_t)BAT * plane;
    const size_t baseb = (size_t)b * plane;
    const size_t basec = baseb + x;

    // Scalar uniforms (edge path + packed-constant sources)
    const float energy_v = fabsf(*p_ev)  + 0.001f;
    const float energy_i = fabsf(*p_ei)  + 0.001f;
    const float kBT      = fabsf(*p_kbt) + 0.001f;
    const float kappa_v  = fabsf(*p_kv)  + 0.001f;
    const float kappa_i  = fabsf(*p_ki)  + 0.001f;
    const float kappa_e  = fabsf(*p_ke)  + 0.001f;
    const float diff_v   = fabsf(*p_dv)  + 0.001f;
    const float diff_i   = fabsf(*p_di)  + 0.001f;
    const float Lp       = fabsf(*p_L)   + 0.001f;
    const float kBTln2   = kBT * LN2F;
    const float inv_kBT  = 1.0f / kBT;
    const float dvk      = DTV * diff_v * inv_kBT;
    const float dik      = DTV * diff_i * inv_kBT;

    // Packed uniform constants
    const u64 M4    = pk(-4.0f, -4.0f);
    const u64 NEG1  = pk(-1.0f, -1.0f);
    const u64 ONE2  = pk(1.0f, 1.0f);
    const u64 EV2   = pk(energy_v, energy_v);
    const u64 EI2   = pk(energy_i, energy_i);
    const u64 KBTL2 = pk(kBTln2, kBTln2);
    const u64 NKV2  = pk(-kappa_v, -kappa_v);
    const u64 NKI2  = pk(-kappa_i, -kappa_i);
    const u64 NKE2  = pk(-kappa_e, -kappa_e);
    const u64 DVK2  = pk(dvk, dvk);
    const u64 DIK2  = pk(dik, dik);
    const u64 NLPDT = pk(-DTV * Lp, -DTV * Lp);

#define ROFF(row) ((size_t)(((unsigned)(row) & (W - 1)) << 10))
#define LDR(p, off) (*(const Row*)((p) + basec + (off)))

    const bool edge = (lane == 0) | (lane == 31);
    const int  eo1  = (lane == 0) ? ((x - 1) & (W - 1)) : ((x + 4) & (W - 1));
    const int  eo2  = (lane == 0) ? ((x - 2) & (W - 1)) : ((x + 5) & (W - 1));
#define LDS1(p, col, off) ((p)[baseb + (off) + (col)])

    // ---- pipeline init ----
    const size_t offm1 = ROFF(y0 - 2), off0 = ROFF(y0 - 1), offp1 = ROFF(y0);

    Row cvm1 = LDR(cv_g,  offm1), cv0 = LDR(cv_g,  off0), cvp1 = LDR(cv_g,  offp1);
    Row cim1 = LDR(ci_g,  offm1), ci0 = LDR(ci_g,  off0), cip1 = LDR(ci_g,  offp1);
    Row etm1 = LDR(eta_g, offm1), et0 = LDR(eta_g, off0), etp1 = LDR(eta_g, offp1);

    float hcv_a = 0.f, hcv_b = 0.f, hcv_c = 0.f;
    float hci_a = 0.f, hci_b = 0.f, hci_c = 0.f;
    float het_b = 0.f, het_c = 0.f;
    float gcv_b = 0.f, gcv_c = 0.f, gci_b = 0.f, gci_c = 0.f;
    if (edge) {
        hcv_a = LDS1(cv_g,  eo1, offm1); hcv_b = LDS1(cv_g,  eo1, off0); hcv_c = LDS1(cv_g,  eo1, offp1);
        hci_a = LDS1(ci_g,  eo1, offm1); hci_b = LDS1(ci_g,  eo1, off0); hci_c = LDS1(ci_g,  eo1, offp1);
        het_b = LDS1(eta_g, eo1, off0);  het_c = LDS1(eta_g, eo1, offp1);
        gcv_b = LDS1(cv_g,  eo2, off0);  gcv_c = LDS1(cv_g,  eo2, offp1);
        gci_b = LDS1(ci_g,  eo2, off0);  gci_c = LDS1(ci_g,  eo2, offp1);
    }

    Row dvA, dvB, diA, diB;
    float hpdv = 0.f, hpdi = 0.f;

    #pragma unroll 2
    for (int i = 0; i < RPB + 2; i++) {
        const int ri = y0 - 1 + i;

        // ---- issue loads of row ri+2 (consumed NEXT iteration) ----
        Row cvp2, cip2, etp2;
        float hcv_d = 0.f, hci_d = 0.f, het_d = 0.f, gcv_d = 0.f, gci_d = 0.f;
        if (i <= RPB) {
            const size_t offp2 = ROFF(ri + 2);
            cvp2 = LDR(cv_g,  offp2);
            cip2 = LDR(ci_g,  offp2);
            etp2 = LDR(eta_g, offp2);
            if (edge) {
                hcv_d = LDS1(cv_g,  eo1, offp2);
                hci_d = LDS1(ci_g,  eo1, offp2);
                het_d = LDS1(eta_g, eo1, offp2);
                gcv_d = LDS1(cv_g,  eo2, offp2);
                gci_d = LDS1(ci_g,  eo2, offp2);
            }
        }

        // ---- unpack current rows ----
        float cvf0, cvf1, cvf2, cvf3; upk(cv0.p0, cvf0, cvf1); upk(cv0.p1, cvf2, cvf3);
        float cif0, cif1, cif2, cif3; upk(ci0.p0, cif0, cif1); upk(ci0.p1, cif2, cif3);
        float etf0, etf1, etf2, etf3; upk(et0.p0, etf0, etf1); upk(et0.p1, etf2, etf3);

        // ---- x-neighbors via shuffle ----
        float cvL = __shfl_up_sync(0xffffffffu, cvf3, 1);
        float ciL = __shfl_up_sync(0xffffffffu, cif3, 1);
        float etL = __shfl_up_sync(0xffffffffu, etf3, 1);
        float cvR = __shfl_down_sync(0xffffffffu, cvf0, 1);
        float ciR = __shfl_down_sync(0xffffffffu, cif0, 1);
        float etR = __shfl_down_sync(0xffffffffu, etf0, 1);
        if (lane == 0)  { cvL = hcv_b; ciL = hci_b; etL = het_b; }
        if (lane == 31) { cvR = hcv_b; ciR = hci_b; etR = het_b; }

        // ---- packed Laplacians of row ri ----
        const u64 midcv = pk(cvf1, cvf2);
        const u64 midci = pk(cif1, cif2);
        const u64 midet = pk(etf1, etf2);
        const u64 lcv0 = fma2(cv0.p0, M4, add2(add2(pk(cvL, cvf0), midcv), add2(cvm1.p0, cvp1.p0)));
        const u64 lcv1 = fma2(cv0.p1, M4, add2(add2(midcv, pk(cvf3, cvR)), add2(cvm1.p1, cvp1.p1)));
        const u64 lci0 = fma2(ci0.p0, M4, add2(add2(pk(ciL, cif0), midci), add2(cim1.p0, cip1.p0)));
        const u64 lci1 = fma2(ci0.p1, M4, add2(add2(midci, pk(cif3, ciR)), add2(cim1.p1, cip1.p1)));
        const u64 let0 = fma2(et0.p0, M4, add2(add2(pk(etL, etf0), midet), add2(etm1.p0, etp1.p0)));
        const u64 let1 = fma2(et0.p1, M4, add2(add2(midet, pk(etf3, etR)), add2(etm1.p1, etp1.p1)));

        // ---- cs (packed) + scalar logs (MUFU.LG2) ----
        const u64 cs0 = fma2(add2(cv0.p0, ci0.p0), NEG1, ONE2);
        const u64 cs1 = fma2(add2(cv0.p1, ci0.p1), NEG1, ONE2);
        float csf0, csf1, csf2, csf3; upk(cs0, csf0, csf1); upk(cs1, csf2, csf3);

        const u64 gcv0 = pk(__log2f(fmaxf(cvf0, EPSV)), __log2f(fmaxf(cvf1, EPSV)));
        const u64 gcv1 = pk(__log2f(fmaxf(cvf2, EPSV)), __log2f(fmaxf(cvf3, EPSV)));
        const u64 gci0 = pk(__log2f(fmaxf(cif0, EPSV)), __log2f(fmaxf(cif1, EPSV)));
        const u64 gci1 = pk(__log2f(fmaxf(cif2, EPSV)), __log2f(fmaxf(cif3, EPSV)));
        const u64 gcs0 = pk(__log2f(fmaxf(csf0, EPSV)), __log2f(fmaxf(csf1, EPSV)));
        const u64 gcs1 = pk(__log2f(fmaxf(csf2, EPSV)), __log2f(fmaxf(csf3, EPSV)));

        // ---- packed dF + eta_new, per pair ----
        Row dvC, diC;
        u64 en0, en1;
        #pragma unroll
        for (int j = 0; j < 2; j++) {
            const u64 cv  = j ? cv0.p1 : cv0.p0;
            const u64 ci  = j ? ci0.p1 : ci0.p0;
            const u64 et  = j ? et0.p1 : et0.p0;
            const u64 cs  = j ? cs1 : cs0;
            const u64 gcv = j ? gcv1 : gcv0;
            const u64 gci = j ? gci1 : gci0;
            const u64 gcs = j ? gcs1 : gcs0;
            const u64 lcv = j ? lcv1 : lcv0;
            const u64 lci = j ? lci1 : lci0;
            const u64 let = j ? let1 : let0;

            const u64 ngcs = mul2(gcs, NEG1);
            const u64 dglv = add2(gcv, ngcs);
            const u64 dgli = add2(gci, ngcs);
            const u64 em1  = add2(et, NEG1);
            const u64 h    = mul2(em1, em1);
            const u64 jj   = mul2(et, et);
            const u64 dfsv = fma2(dglv, KBTL2, EV2);
            const u64 dfsi = fma2(dgli, KBTL2, EI2);
            const u64 ucv  = add2(cv, NEG1);

            const u64 dv = fma2(h, dfsv, fma2(jj, add2(ucv, ucv), mul2(lcv, NKV2)));
            const u64 di = fma2(h, dfsi, fma2(jj, add2(ci,  ci ), mul2(lci, NKI2)));

            u64 t = mul2(cv, gcv);
            t = fma2(ci, gci, t);
            t = fma2(cs, gcs, t);
            const u64 fs  = fma2(t, KBTL2, fma2(ci, EI2, mul2(cv, EV2)));
            const u64 fv  = fma2(ucv, ucv, mul2(ci, ci));
            const u64 dFe = fma2(fs, add2(em1, em1), fma2(fv, add2(et, et), mul2(let, NKE2)));
            const u64 en  = fma2(dFe, NLPDT, et);

            if (j) { dvC.p1 = dv; diC.p1 = di; en1 = en; }
            else   { dvC.p0 = dv; diC.p0 = di; en0 = en; }
        }

        if (i >= 1 && i <= RPB) {
            float e0, e1, e2, e3; upk(en0, e0, e1); upk(en1, e2, e3);
            *(float4*)&out[2 * fld + basec + ROFF(ri)] =
                make_float4(__saturatef(e0), __saturatef(e1), __saturatef(e2), __saturatef(e3));
        }

        // ---- halo dF at (eo1, ri): edge lanes, scalar ----
        float hdv = 0.f, hdi = 0.f;
        if (edge) {
            const float inner_cv = (lane == 0) ? cvf0 : cvf3;
            const float inner_ci = (lane == 0) ? cif0 : cif3;
            const float lap_hcv = gcv_b + inner_cv + hcv_a + hcv_c - 4.0f * hcv_b;
            const float lap_hci = gci_b + inner_ci + hci_a + hci_c - 4.0f * hci_b;

            const float cs  = 1.0f - hcv_b - hci_b;
            const float gv  = __log2f(fmaxf(hcv_b, EPSV));
            const float gi  = __log2f(fmaxf(hci_b, EPSV));
            const float gs  = __log2f(fmaxf(cs, EPSV));
            const float em1 = het_b - 1.0f;
            const float h   = em1 * em1;
            const float jj  = het_b * het_b;

            hdv = h * (energy_v + kBTln2 * (gv - gs)) + jj * (2.0f * (hcv_b - 1.0f)) - kappa_v * lap_hcv;
            hdi = h * (energy_i + kBTln2 * (gi - gs)) + jj * (2.0f * hci_b)          - kappa_i * lap_hci;
        }

        // ---- output row ro = ri-1 ----
        if (i >= 2) {
            float bv0, bv1, bv2, bv3; upk(dvB.p0, bv0, bv1); upk(dvB.p1, bv2, bv3);
            float bi0, bi1, bi2, bi3; upk(diB.p0, bi0, bi1); upk(diB.p1, bi2, bi3);

            float eLv = __shfl_up_sync(0xffffffffu, bv3, 1);
            float eLi = __shfl_up_sync(0xffffffffu, bi3, 1);
            float eRv = __shfl_down_sync(0xffffffffu, bv0, 1);
            float eRi = __shfl_down_sync(0xffffffffu, bi0, 1);
            if (lane == 0)  { eLv = hpdv; eLi = hpdi; }
            if (lane == 31) { eRv = hpdv; eRi = hpdi; }

            const u64 midv = pk(bv1, bv2);
            const u64 midi = pk(bi1, bi2);
            const u64 ldv0 = fma2(dvB.p0, M4, add2(add2(pk(eLv, bv0), midv), add2(dvA.p0, dvC.p0)));
            const u64 ldv1 = fma2(dvB.p1, M4, add2(add2(midv, pk(bv3, eRv)), add2(dvA.p1, dvC.p1)));
            const u64 ldi0 = fma2(diB.p0, M4, add2(add2(pk(eLi, bi0), midi), add2(diA.p0, diC.p0)));
            const u64 ldi1 = fma2(diB.p1, M4, add2(add2(midi, pk(bi3, eRi)), add2(diA.p1, diC.p1)));

            // cvm1 holds field row ri-1 = ro
            const u64 nv0 = fma2(mul2(cvm1.p0, DVK2), ldv0, cvm1.p0);
            const u64 nv1 = fma2(mul2(cvm1.p1, DVK2), ldv1, cvm1.p1);
            const u64 ni0 = fma2(mul2(cim1.p0, DIK2), ldi0, cim1.p0);
            const u64 ni1 = fma2(mul2(cim1.p1, DIK2), ldi1, cim1.p1);

            float v0, v1, v2, v3; upk(nv0, v0, v1); upk(nv1, v2, v3);
            float w0, w1, w2, w3; upk(ni0, w0, w1); upk(ni1, w2, w3);

            const size_t o = basec + ROFF(ri - 1);
            *(float4*)&out[o] =
                make_float4(__saturatef(v0), __saturatef(v1), __saturatef(v2), __saturatef(v3));
            *(float4*)&out[fld + o] =
                make_float4(__saturatef(w0), __saturatef(w1), __saturatef(w2), __saturatef(w3));
        }

        // ---- rotate (renamed away by unroll) ----
        dvA = dvB; dvB = dvC; diA = diB; diB = diC;
        hpdv = hdv; hpdi = hdi;
        cvm1 = cv0; cv0 = cvp1; cvp1 = cvp2;
        cim1 = ci0; ci0 = cip1; cip1 = cip2;
        etm1 = et0; et0 = etp1; etp1 = etp2;
        hcv_a = hcv_b; hcv_b = hcv_c; hcv_c = hcv_d;
        hci_a = hci_b; hci_b = hci_c; hci_c = hci_d;
        het_b = het_c; het_c = het_d;
        gcv_b = gcv_c; gcv_c = gcv_d;
        gci_b = gci_c; gci_c = gci_d;
    }
#undef ROFF
#undef LDR
#undef LDS1
}

extern "C" void kernel_launch(void* const* d_in, const int* in_sizes, int n_in,
                              void* d_out, int out_size)
{
    const float* cv  = (const float*)d_in[0];
    const float* ci  = (const float*)d_in[1];
    const float* eta = (const float*)d_in[2];
    const float* ev  = (const float*)d_in[3];
    const float* ei  = (const float*)d_in[4];
    const float* kbt = (const float*)d_in[5];
    const float* kv  = (const float*)d_in[6];
    const float* ki  = (const float*)d_in[7];
    const float* ke  = (const float*)d_in[8];
    const float* dv  = (const float*)d_in[9];
    const float* di  = (const float*)d_in[10];
    const float* L   = (const float*)d_in[11];
    float* out = (float*)d_out;

    dim3 block(128, 1, 1);
    dim3 grid(2, W / RPB, BAT);
    irr_warp_kernel<<<grid, block>>>(cv, ci, eta, ev, ei, kbt, kv, ki, ke,
                                     dv, di, L, out);
}

// round 17
// speedup vs baseline: 1.4509x; 1.4509x over previous
#include <cuda_runtime.h>
#include <cuda_bf16.h>

// IrradiationSingleTimestep — round 16: revert to round-14 structure
// (barrier-free warp-strip rolling stencil, RPB=16, unroll 2, deep prefetch),
// plus three safe scalar trims: __log2f with ln2 folded into kBT,
// __saturatef clamps, and DT*diff/kBT premultiplied constants.
// (round-15 f32x2 packing regressed: pack/unpack churn + reg-pair pressure.)

#define W     1024
#define BAT   8
#define RPB   16
#define EPSV  1e-6f
#define DTV   1e-2f
#define LN2F  0.69314718055994530942f

__device__ __forceinline__ float4 lap4(float4 c, float L, float R, float4 u, float4 d) {
    float4 r;
    r.x = L   + c.y + u.x + d.x - 4.0f * c.x;
    r.y = c.x + c.z + u.y + d.y - 4.0f * c.y;
    r.z = c.y + c.w + u.z + d.z - 4.0f * c.z;
    r.w = c.z + R   + u.w + d.w - 4.0f * c.w;
    return r;
}
__device__ __forceinline__ float lane_of(const float4& v, int k) {
    return k == 0 ? v.x : (k == 1 ? v.y : (k == 2 ? v.z : v.w));
}
__device__ __forceinline__ void set_lane(float4& v, int k, float x) {
    if (k == 0) v.x = x; else if (k == 1) v.y = x; else if (k == 2) v.z = x; else v.w = x;
}

__global__ __launch_bounds__(128, 4)
void irr_warp_kernel(const float* __restrict__ cv_g,
                     const float* __restrict__ ci_g,
                     const float* __restrict__ eta_g,
                     const float* __restrict__ p_ev,
                     const float* __restrict__ p_ei,
                     const float* __restrict__ p_kbt,
                     const float* __restrict__ p_kv,
                     const float* __restrict__ p_ki,
                     const float* __restrict__ p_ke,
                     const float* __restrict__ p_dv,
                     const float* __restrict__ p_di,
                     const float* __restrict__ p_L,
                     float* __restrict__ out)
{
    const int lane  = threadIdx.x & 31;
    const int wl    = threadIdx.x >> 5;
    const int strip = blockIdx.x * 4 + wl;
    const int x     = (strip << 7) + (lane << 2);
    const int y0    = blockIdx.y * RPB;
    const int b     = blockIdx.z;

    const size_t plane = (size_t)W * W;
    const size_t fld   = (size_t)BAT * plane;
    const size_t baseb = (size_t)b * plane;
    const size_t basec = baseb + x;

    const float energy_v = fabsf(*p_ev)  + 0.001f;
    const float energy_i = fabsf(*p_ei)  + 0.001f;
    const float kBT      = fabsf(*p_kbt) + 0.001f;
    const float kappa_v  = fabsf(*p_kv)  + 0.001f;
    const float kappa_i  = fabsf(*p_ki)  + 0.001f;
    const float kappa_e  = fabsf(*p_ke)  + 0.001f;
    const float diff_v   = fabsf(*p_dv)  + 0.001f;
    const float diff_i   = fabsf(*p_di)  + 0.001f;
    const float Lp       = fabsf(*p_L)   + 0.001f;
    const float kBTln2   = kBT * LN2F;        // fold ln2 of log2 into kBT
    const float dvk      = DTV * diff_v / kBT;  // premultiplied mobility consts
    const float dik      = DTV * diff_i / kBT;
    const float nLdt     = -DTV * Lp;

#define ROFF(row) ((size_t)(((unsigned)(row) & (W - 1)) << 10))
#define LDV(p, off) (*(const float4*)((p) + basec + (off)))

    const bool edge = (lane == 0) | (lane == 31);
    const int  eo1  = (lane == 0) ? ((x - 1) & (W - 1)) : ((x + 4) & (W - 1));
    const int  eo2  = (lane == 0) ? ((x - 2) & (W - 1)) : ((x + 5) & (W - 1));
#define LDS1(p, col, off) ((p)[baseb + (off) + (col)])

    // ---- pipeline init ----
    const size_t offm1 = ROFF(y0 - 2), off0 = ROFF(y0 - 1), offp1 = ROFF(y0);

    float4 cvm1 = LDV(cv_g,  offm1), cv0 = LDV(cv_g,  off0), cvp1 = LDV(cv_g,  offp1);
    float4 cim1 = LDV(ci_g,  offm1), ci0 = LDV(ci_g,  off0), cip1 = LDV(ci_g,  offp1);
    float4 etm1 = LDV(eta_g, offm1), et0 = LDV(eta_g, off0), etp1 = LDV(eta_g, offp1);

    float hcv_a = 0.f, hcv_b = 0.f, hcv_c = 0.f;
    float hci_a = 0.f, hci_b = 0.f, hci_c = 0.f;
    float het_b = 0.f, het_c = 0.f;
    float gcv_b = 0.f, gcv_c = 0.f, gci_b = 0.f, gci_c = 0.f;
    if (edge) {
        hcv_a = LDS1(cv_g,  eo1, offm1); hcv_b = LDS1(cv_g,  eo1, off0); hcv_c = LDS1(cv_g,  eo1, offp1);
        hci_a = LDS1(ci_g,  eo1, offm1); hci_b = LDS1(ci_g,  eo1, off0); hci_c = LDS1(ci_g,  eo1, offp1);
        het_b = LDS1(eta_g, eo1, off0);  het_c = LDS1(eta_g, eo1, offp1);
        gcv_b = LDS1(cv_g,  eo2, off0);  gcv_c = LDS1(cv_g,  eo2, offp1);
        gci_b = LDS1(ci_g,  eo2, off0);  gci_c = LDS1(ci_g,  eo2, offp1);
    }

    float4 dvA, dvB, diA, diB;
    float hpdv = 0.f, hpdi = 0.f;

    #pragma unroll 2
    for (int i = 0; i < RPB + 2; i++) {
        const int ri = y0 - 1 + i;

        // ---- issue loads of row ri+2 (consumed NEXT iteration) ----
        float4 cvp2, cip2, etp2;
        float hcv_d = 0.f, hci_d = 0.f, het_d = 0.f, gcv_d = 0.f, gci_d = 0.f;
        if (i <= RPB) {
            const size_t offp2 = ROFF(ri + 2);
            cvp2 = LDV(cv_g,  offp2);
            cip2 = LDV(ci_g,  offp2);
            etp2 = LDV(eta_g, offp2);
            if (edge) {
                hcv_d = LDS1(cv_g,  eo1, offp2);
                hci_d = LDS1(ci_g,  eo1, offp2);
                het_d = LDS1(eta_g, eo1, offp2);
                gcv_d = LDS1(cv_g,  eo2, offp2);
                gci_d = LDS1(ci_g,  eo2, offp2);
            }
        }

        // ---- field x-neighbors of row ri ----
        float cvL = __shfl_up_sync(0xffffffffu, cv0.w, 1);
        float ciL = __shfl_up_sync(0xffffffffu, ci0.w, 1);
        float etL = __shfl_up_sync(0xffffffffu, et0.w, 1);
        float cvR = __shfl_down_sync(0xffffffffu, cv0.x, 1);
        float ciR = __shfl_down_sync(0xffffffffu, ci0.x, 1);
        float etR = __shfl_down_sync(0xffffffffu, et0.x, 1);
        if (lane == 0)  { cvL = hcv_b; ciL = hci_b; etL = het_b; }
        if (lane == 31) { cvR = hcv_b; ciR = hci_b; etR = het_b; }

        // ---- dF row ri + eta_new ----
        const float4 lcv4 = lap4(cv0, cvL, cvR, cvm1, cvp1);
        const float4 lci4 = lap4(ci0, ciL, ciR, cim1, cip1);
        const float4 let4 = lap4(et0, etL, etR, etm1, etp1);

        float4 dvC, diC, en4;
        #pragma unroll
        for (int k = 0; k < 4; k++) {
            const float cv  = lane_of(cv0, k);
            const float ci  = lane_of(ci0, k);
            const float eta = lane_of(et0, k);

            const float cs  = 1.0f - cv - ci;
            const float gcv = __log2f(fmaxf(cv, EPSV));
            const float gci = __log2f(fmaxf(ci, EPSV));
            const float gcs = __log2f(fmaxf(cs, EPSV));

            const float em1 = eta - 1.0f;
            const float h   = em1 * em1;
            const float jj  = eta * eta;

            const float dfs_dcv = energy_v + kBTln2 * (gcv - gcs);
            const float dfs_dci = energy_i + kBTln2 * (gci - gcs);

            set_lane(dvC, k, h * dfs_dcv + jj * (2.0f * (cv - 1.0f)) - kappa_v * lane_of(lcv4, k));
            set_lane(diC, k, h * dfs_dci + jj * (2.0f * ci)          - kappa_i * lane_of(lci4, k));

            const float fs = energy_v * cv + energy_i * ci
                           + kBTln2 * (cv * gcv + ci * gci + cs * gcs);
            const float cq = cv - 1.0f;
            const float fv = cq * cq + ci * ci;
            const float dFe = fs * (2.0f * em1) + fv * (2.0f * eta)
                            - kappa_e * lane_of(let4, k);
            set_lane(en4, k, __saturatef(eta + nLdt * dFe));
        }

        if (i >= 1 && i <= RPB) {
            *(float4*)&out[2 * fld + basec + ROFF(ri)] = en4;
        }

        // ---- halo dF at (eo1, ri): edge lanes, all inputs prefetched ----
        float hdv = 0.f, hdi = 0.f;
        if (edge) {
            const float inner_cv = (lane == 0) ? cv0.x : cv0.w;
            const float inner_ci = (lane == 0) ? ci0.x : ci0.w;
            const float lap_hcv = gcv_b + inner_cv + hcv_a + hcv_c - 4.0f * hcv_b;
            const float lap_hci = gci_b + inner_ci + hci_a + hci_c - 4.0f * hci_b;

            const float cs = 1.0f - hcv_b - hci_b;
            const float gv = __log2f(fmaxf(hcv_b, EPSV));
            const float gi = __log2f(fmaxf(hci_b, EPSV));
            const float gs = __log2f(fmaxf(cs, EPSV));
            const float em1 = het_b - 1.0f;
            const float h   = em1 * em1;
            const float jj  = het_b * het_b;

            hdv = h * (energy_v + kBTln2 * (gv - gs)) + jj * (2.0f * (hcv_b - 1.0f)) - kappa_v * lap_hcv;
            hdi = h * (energy_i + kBTln2 * (gi - gs)) + jj * (2.0f * hci_b)          - kappa_i * lap_hci;
        }

        // ---- output row ro = ri-1 ----
        if (i >= 2) {
            float eLv = __shfl_up_sync(0xffffffffu, dvB.w, 1);
            float eLi = __shfl_up_sync(0xffffffffu, diB.w, 1);
            float eRv = __shfl_down_sync(0xffffffffu, dvB.x, 1);
            float eRi = __shfl_down_sync(0xffffffffu, diB.x, 1);
            if (lane == 0)  { eLv = hpdv; eLi = hpdi; }
            if (lane == 31) { eRv = hpdv; eRi = hpdi; }

            const float4 ldv = lap4(dvB, eLv, eRv, dvA, dvC);
            const float4 ldi = lap4(diB, eLi, eRi, diA, diC);

            float4 cvn, cin;
            #pragma unroll
            for (int k = 0; k < 4; k++) {
                const float cv = lane_of(cvm1, k);   // field row ri-1
                const float ci = lane_of(cim1, k);
                set_lane(cvn, k, __saturatef(cv + (dvk * cv) * lane_of(ldv, k)));
                set_lane(cin, k, __saturatef(ci + (dik * ci) * lane_of(ldi, k)));
            }
            const size_t o = basec + ROFF(ri - 1);
            *(float4*)&out[o]       = cvn;
            *(float4*)&out[fld + o] = cin;
        }

        // ---- rotate (renamed away by unroll) ----
        dvA = dvB; dvB = dvC; diA = diB; diB = diC;
        hpdv = hdv; hpdi = hdi;
        cvm1 = cv0; cv0 = cvp1; cvp1 = cvp2;
        cim1 = ci0; ci0 = cip1; cip1 = cip2;
        etm1 = et0; et0 = etp1; etp1 = etp2;
        hcv_a = hcv_b; hcv_b = hcv_c; hcv_c = hcv_d;
        hci_a = hci_b; hci_b = hci_c; hci_c = hci_d;
        het_b = het_c; het_c = het_d;
        gcv_b = gcv_c; gcv_c = gcv_d;
        gci_b = gci_c; gci_c = gci_d;
    }
#undef ROFF
#undef LDV
#undef LDS1
}

extern "C" void kernel_launch(void* const* d_in, const int* in_sizes, int n_in,
                              void* d_out, int out_size)
{
    const float* cv  = (const float*)d_in[0];
    const float* ci  = (const float*)d_in[1];
    const float* eta = (const float*)d_in[2];
    const float* ev  = (const float*)d_in[3];
    const float* ei  = (const float*)d_in[4];
    const float* kbt = (const float*)d_in[5];
    const float* kv  = (const float*)d_in[6];
    const float* ki  = (const float*)d_in[7];
    const float* ke  = (const float*)d_in[8];
    const float* dv  = (const float*)d_in[9];
    const float* di  = (const float*)d_in[10];
    const float* L   = (const float*)d_in[11];
    float* out = (float*)d_out;

    dim3 block(128, 1, 1);
    dim3 grid(2, W / RPB, BAT);
    irr_warp_kernel<<<grid, block>>>(cv, ci, eta, ev, ei, kbt, kv, ki, ke,
                                     dv, di, L, out);
}